// round 5
// baseline (speedup 1.0000x reference)
#include <cuda_runtime.h>
#include <cuda_fp16.h>
#include <math.h>
#include <stdint.h>

#define Nn 65536
#define Dd 1024
#define Ss 512
#define Kslots 64
#define AGG_BLOCKS 256
#define AGG_ROWS (Nn / AGG_BLOCKS)

// ======================= helpers =============================================
__device__ __forceinline__ uint32_t smem_u32(const void* p) {
    uint32_t a;
    asm("{ .reg .u64 t; cvta.to.shared.u64 t, %1; cvt.u32.u64 %0, t; }" : "=r"(a) : "l"(p));
    return a;
}
__device__ __forceinline__ void mbar_init(uint32_t a, uint32_t cnt) {
    asm volatile("mbarrier.init.shared.b64 [%0], %1;" :: "r"(a), "r"(cnt) : "memory");
}
__device__ __forceinline__ void mbar_expect_tx(uint32_t a, uint32_t bytes) {
    asm volatile("mbarrier.arrive.expect_tx.shared.b64 _, [%0], %1;"
                 :: "r"(a), "r"(bytes) : "memory");
}
__device__ __forceinline__ void mbar_wait(uint32_t a, uint32_t ph) {
    asm volatile(
        "{\n\t.reg .pred P;\n"
        "W%=:\n\t"
        "mbarrier.try_wait.parity.acquire.cta.shared::cta.b64 P, [%0], %1, 0x989680;\n\t"
        "@P bra D%=;\n\t"
        "bra W%=;\n"
        "D%=:\n\t}"
        :: "r"(a), "r"(ph) : "memory");
}
__device__ __forceinline__ void bulk_ldg128(uint32_t dst, const void* src, uint32_t mbar) {
    asm volatile(
        "cp.async.bulk.shared::cluster.global.mbarrier::complete_tx::bytes [%0], [%1], 128, [%2];"
        :: "r"(dst), "l"(src), "r"(mbar) : "memory");
}
__device__ __forceinline__ void ldsm4(uint32_t* r, uint32_t addr) {
    asm volatile("ldmatrix.sync.aligned.m8n8.x4.shared.b16 {%0,%1,%2,%3}, [%4];"
                 : "=r"(r[0]), "=r"(r[1]), "=r"(r[2]), "=r"(r[3]) : "r"(addr));
}
__device__ __forceinline__ void hmma16(float* c, const uint32_t* a, const uint32_t* b) {
    asm volatile(
        "mma.sync.aligned.m16n8k16.row.col.f32.f16.f16.f32 "
        "{%0,%1,%2,%3}, {%4,%5,%6,%7}, {%8,%9}, {%0,%1,%2,%3};"
        : "+f"(c[0]), "+f"(c[1]), "+f"(c[2]), "+f"(c[3])
        : "r"(a[0]), "r"(a[1]), "r"(a[2]), "r"(a[3]), "r"(b[0]), "r"(b[1]));
}
__device__ __forceinline__ void split2h(float x, __half& h, __half& l) {
    h = __float2half(x);
    l = __float2half(x - __half2float(h));
}

// ======================= device global scratch ===============================
// A-side activations: fp16 hi/lo planes
__device__ __align__(1024) __half g_xh[(size_t)Nn * Dd], g_xl[(size_t)Nn * Dd];
__device__ __align__(1024) __half g_qh[(size_t)Nn * Ss], g_ql[(size_t)Nn * Ss];
__device__ __align__(1024) __half g_ath[(size_t)Nn * Kslots], g_atl[(size_t)Nn * Kslots];
__device__ __align__(1024) __half g_rh[(size_t)Nn * Ss], g_rl[(size_t)Nn * Ss];
__device__ __align__(1024) __half g_hh[(size_t)Nn * Dd], g_hl[(size_t)Nn * Dd];
// fp32 intermediates
__device__ __align__(1024) float g_ro[(size_t)Nn * Dd];
__device__ __align__(1024) float g_logits[(size_t)Nn * Kslots];
__device__ __align__(1024) float g_erase[(size_t)Nn * Ss];
__device__ __align__(1024) float g_content[(size_t)Nn * Ss];
__device__ __align__(1024) float g_weighted[(size_t)Nn * Kslots];
__device__ float g_gate[Nn];
__device__ __align__(1024) float g_partE[(size_t)AGG_BLOCKS * Kslots * Ss];
__device__ __align__(1024) float g_partW[(size_t)AGG_BLOCKS * Kslots * Ss];
// B-side (weights), single-plane fp16, [n,k] K-major
__device__ __align__(1024) __half g_wqT[(size_t)Ss * Dd];
__device__ __align__(1024) __half g_woT[(size_t)Dd * Ss];
__device__ __align__(1024) __half g_wall[(size_t)(3 * Ss) * Dd];   // [Wa;We;Wc]^T
__device__ __align__(1024) __half g_kp[(size_t)Kslots * Ss];       // Kp  [64,512]
__device__ __align__(1024) __half g_vT[(size_t)Ss * Kslots];       // V^T [512,64]
__device__ __align__(1024) __half g_st[(size_t)Kslots * Ss];       // state [64,512]

// ======================= fp16 2-term split GEMM (mma.sync) ===================
// C[M,Nc] = act( (Ah+Al) @ B^T );  A,B stored [rows,K] K-major fp16.
// 2-term: Ah*B + Al*B, fp32 accumulate in registers.
// Loads via cp.async.bulk (128B rows) into 144B-stride smem (no swizzle needed).
// MODE: 0 fp32, 1 fp32*scale, 4 split fp16 out,
//       5 fused-triple over Nc=1536: seg0 split fp16, seg1 sigmoid+bias, seg2 tanh+bias2
template <int BN, int MODE>
__global__ void __launch_bounds__(256, 1)
hgemm(const __half* __restrict__ Ah, const __half* __restrict__ Al,
      const __half* __restrict__ B,
      int Kd, int Nc,
      float* __restrict__ Cf, float* __restrict__ Cf2,
      __half* __restrict__ Chi, __half* __restrict__ Clo,
      const float* __restrict__ bias, const float* __restrict__ bias2, float scale)
{
    constexpr int BM = 128;
    constexpr int RS = 144;                 // smem row stride (bytes)
    constexpr int NROWS = 2 * BM + BN;      // Ah rows, Al rows, B rows
    constexpr int STAGE = NROWS * RS;
    constexpr uint32_t TX = NROWS * 128;    // transferred bytes per stage
    constexpr int ALo = BM * RS;
    constexpr int Bo = 2 * BM * RS;
    constexpr int NWN = (BN == 128) ? 4 : 2;
    constexpr int NWM = 8 / NWN;
    constexpr int WM = BM / NWM;            // 64 or 32
    constexpr int MF = WM / 16;             // 4 or 2
    constexpr int NF = (BN / NWN) / 8;      // 4

    extern __shared__ char smem_raw[];
    __shared__ __align__(8) uint64_t s_mb[2];
    uint32_t dbase = (smem_u32(smem_raw) + 1023u) & ~1023u;
    uint32_t mb = smem_u32(s_mb);

    int tid = threadIdx.x, w = tid >> 5, lane = tid & 31;
    int row0 = blockIdx.y * BM, col0 = blockIdx.x * BN;
    int wm0 = (w / NWN) * WM, wn0 = (w % NWN) * (BN / NWN);
    int nch = Kd >> 6;

    if (tid == 0) { mbar_init(mb + 0, 1); mbar_init(mb + 8, 1); }
    __syncthreads();

    float acc[MF][NF][4];
#pragma unroll
    for (int i = 0; i < MF; i++)
#pragma unroll
        for (int j = 0; j < NF; j++)
#pragma unroll
            for (int u = 0; u < 4; u++) acc[i][j][u] = 0.f;

    auto issue = [&](int c) {
        int s = c & 1;
        if (tid == 0) mbar_expect_tx(mb + 8 * s, TX);
        uint32_t sbase = dbase + s * STAGE;
        int k0 = c << 6;
        for (int rr = tid; rr < NROWS; rr += 256) {
            const __half* src;
            if (rr < BM)
                src = Ah + (size_t)(row0 + rr) * Kd + k0;
            else if (rr < 2 * BM)
                src = Al + (size_t)(row0 + rr - BM) * Kd + k0;
            else
                src = B + (size_t)(col0 + rr - 2 * BM) * Kd + k0;
            bulk_ldg128(sbase + rr * RS, (const void*)src, mb + 8 * s);
        }
    };

    issue(0);
    for (int c = 0; c < nch; c++) {
        if (c + 1 < nch) issue(c + 1);
        mbar_wait(mb + 8 * (c & 1), (c >> 1) & 1);
        uint32_t sb = dbase + (c & 1) * STAGE;
#pragma unroll
        for (int ks = 0; ks < 4; ks++) {
            uint32_t ah[MF][4], al_[MF][4];
#pragma unroll
            for (int i = 0; i < MF; i++) {
                uint32_t addr = sb + (uint32_t)(wm0 + i * 16 + (lane & 15)) * RS +
                                ks * 32 + ((lane >> 4) << 4);
                ldsm4(ah[i], addr);
                ldsm4(al_[i], addr + ALo);
            }
            uint32_t b[NF][2];
#pragma unroll
            for (int j2 = 0; j2 < NF / 2; j2++) {
                uint32_t addr = sb + Bo +
                                (uint32_t)(wn0 + j2 * 16 + (lane & 7) + ((lane >> 4) << 3)) * RS +
                                ks * 32 + (((lane >> 3) & 1) << 4);
                uint32_t t[4];
                ldsm4(t, addr);
                b[2 * j2][0] = t[0]; b[2 * j2][1] = t[1];
                b[2 * j2 + 1][0] = t[2]; b[2 * j2 + 1][1] = t[3];
            }
#pragma unroll
            for (int i = 0; i < MF; i++)
#pragma unroll
                for (int j = 0; j < NF; j++) hmma16(acc[i][j], ah[i], b[j]);
#pragma unroll
            for (int i = 0; i < MF; i++)
#pragma unroll
                for (int j = 0; j < NF; j++) hmma16(acc[i][j], al_[i], b[j]);
        }
        __syncthreads();   // all reads of this stage done before it is refilled
    }

    // ---- epilogue ----
    int seg = col0 >> 9;   // MODE 5: uniform per CTA (BN=128 divides 512)
#pragma unroll
    for (int i = 0; i < MF; i++) {
#pragma unroll
        for (int j = 0; j < NF; j++) {
            int r = row0 + wm0 + i * 16 + (lane >> 2);
            int cp = col0 + wn0 + j * 8 + ((lane & 3) << 1);
#pragma unroll
            for (int half = 0; half < 2; half++) {
                int rr = r + half * 8;
                float x0 = acc[i][j][half * 2 + 0];
                float x1 = acc[i][j][half * 2 + 1];
                if (MODE == 4) {
                    __half h0, l0, h1, l1;
                    split2h(x0, h0, l0);
                    split2h(x1, h1, l1);
                    __half2 ph; ph.x = h0; ph.y = h1;
                    __half2 pl; pl.x = l0; pl.y = l1;
                    *reinterpret_cast<__half2*>(&Chi[(size_t)rr * Nc + cp]) = ph;
                    *reinterpret_cast<__half2*>(&Clo[(size_t)rr * Nc + cp]) = pl;
                } else if (MODE == 5) {
                    int colL = cp - seg * 512;
                    if (seg == 0) {
                        __half h0, l0, h1, l1;
                        split2h(x0, h0, l0);
                        split2h(x1, h1, l1);
                        __half2 ph; ph.x = h0; ph.y = h1;
                        __half2 pl; pl.x = l0; pl.y = l1;
                        *reinterpret_cast<__half2*>(&Chi[(size_t)rr * Ss + colL]) = ph;
                        *reinterpret_cast<__half2*>(&Clo[(size_t)rr * Ss + colL]) = pl;
                    } else if (seg == 1) {
                        float2 o;
                        o.x = 1.f / (1.f + __expf(-(x0 + bias[colL])));
                        o.y = 1.f / (1.f + __expf(-(x1 + bias[colL + 1])));
                        *reinterpret_cast<float2*>(&Cf[(size_t)rr * Ss + colL]) = o;
                    } else {
                        float2 o;
                        o.x = tanhf(x0 + bias2[colL]);
                        o.y = tanhf(x1 + bias2[colL + 1]);
                        *reinterpret_cast<float2*>(&Cf2[(size_t)rr * Ss + colL]) = o;
                    }
                } else {
                    if (MODE == 1) { x0 *= scale; x1 *= scale; }
                    float2 o; o.x = x0; o.y = x1;
                    *reinterpret_cast<float2*>(&Cf[(size_t)rr * Nc + cp]) = o;
                }
            }
        }
    }
}

// ======================= prep / elementwise kernels ==========================
__global__ void convert_split_kernel(const float* __restrict__ in,
                                     __half* __restrict__ oh, __half* __restrict__ ol,
                                     size_t n4) {
    size_t i = (size_t)blockIdx.x * blockDim.x + threadIdx.x;
    if (i >= n4) return;
    float4 v = reinterpret_cast<const float4*>(in)[i];
    __half h0, l0, h1, l1, h2, l2, h3, l3;
    split2h(v.x, h0, l0); split2h(v.y, h1, l1);
    split2h(v.z, h2, l2); split2h(v.w, h3, l3);
    __half2 a, b, c, d;
    a.x = h0; a.y = h1; b.x = h2; b.y = h3;
    c.x = l0; c.y = l1; d.x = l2; d.y = l3;
    reinterpret_cast<__half2*>(oh)[i * 2] = a;
    reinterpret_cast<__half2*>(oh)[i * 2 + 1] = b;
    reinterpret_cast<__half2*>(ol)[i * 2] = c;
    reinterpret_cast<__half2*>(ol)[i * 2 + 1] = d;
}

// W[R,C] fp32 -> out[C,R] fp16 (transpose, single plane)
__global__ void transpose_h_kernel(const float* __restrict__ W,
                                   __half* __restrict__ T, int R, int C) {
    __shared__ float t[32][33];
    int c0 = blockIdx.x * 32, r0 = blockIdx.y * 32;
    int tx = threadIdx.x, ty = threadIdx.y;
#pragma unroll
    for (int i = 0; i < 32; i += 8)
        t[ty + i][tx] = W[(size_t)(r0 + ty + i) * C + c0 + tx];
    __syncthreads();
#pragma unroll
    for (int i = 0; i < 32; i += 8)
        T[(size_t)(c0 + ty + i) * R + r0 + tx] = __float2half(t[tx][ty + i]);
}

__global__ void kv_kernel(const float* __restrict__ state,
                          const float* __restrict__ Wk,
                          const float* __restrict__ Wv) {
    int j = blockIdx.x;
    __shared__ float srow[Ss];
    for (int c = threadIdx.x; c < Ss; c += blockDim.x) srow[c] = state[j * Ss + c];
    __syncthreads();
    for (int c = threadIdx.x; c < Ss; c += blockDim.x) {
        float ak = 0.f, av = 0.f;
        for (int t = 0; t < Ss; t++) {
            float s = srow[t];
            ak += s * Wk[t * Ss + c];
            av += s * Wv[t * Ss + c];
        }
        g_kp[j * Ss + c] = __float2half(ak);
        g_vT[c * Kslots + j] = __float2half(av);
        g_st[j * Ss + c] = __float2half(srow[c]);
    }
}

template <bool SPLIT_OUT>
__global__ void softmax_kernel(const float* __restrict__ logits,
                               const float* __restrict__ gate,
                               __half* __restrict__ oh, __half* __restrict__ ol,
                               float* __restrict__ of) {
    int row = blockIdx.x * blockDim.y + threadIdx.y;
    int lane = threadIdx.x;
    float v0 = logits[(size_t)row * 64 + lane];
    float v1 = logits[(size_t)row * 64 + 32 + lane];
    float m = fmaxf(v0, v1);
#pragma unroll
    for (int o = 16; o; o >>= 1) m = fmaxf(m, __shfl_xor_sync(0xffffffffu, m, o));
    float e0 = __expf(v0 - m), e1 = __expf(v1 - m);
    float s = e0 + e1;
#pragma unroll
    for (int o = 16; o; o >>= 1) s += __shfl_xor_sync(0xffffffffu, s, o);
    float inv = 1.f / s;
    if (!SPLIT_OUT) inv *= gate[row];
    float a0 = e0 * inv, a1 = e1 * inv;
    if (SPLIT_OUT) {
        __half h, l;
        split2h(a0, h, l);
        oh[(size_t)row * 64 + lane] = h; ol[(size_t)row * 64 + lane] = l;
        split2h(a1, h, l);
        oh[(size_t)row * 64 + 32 + lane] = h; ol[(size_t)row * 64 + 32 + lane] = l;
    } else {
        of[(size_t)row * 64 + lane] = a0;
        of[(size_t)row * 64 + 32 + lane] = a1;
    }
}

__global__ void ln_gate_kernel(const float* __restrict__ nf,
                               const float* __restrict__ ro,
                               const float* __restrict__ gamma,
                               const float* __restrict__ beta,
                               const float* __restrict__ Wg,
                               const float* __restrict__ bg,
                               float* __restrict__ h,
                               __half* __restrict__ hh, __half* __restrict__ hl,
                               float* __restrict__ gate) {
    int row = blockIdx.x;
    int tid = threadIdx.x;
    __shared__ float sh[16];
    float4 a = reinterpret_cast<const float4*>(nf + (size_t)row * Dd)[tid];
    float4 b = reinterpret_cast<const float4*>(ro + (size_t)row * Dd)[tid];
    float v0 = a.x + b.x, v1 = a.y + b.y, v2 = a.z + b.z, v3 = a.w + b.w;
    float s = v0 + v1 + v2 + v3;
    float sq = v0 * v0 + v1 * v1 + v2 * v2 + v3 * v3;
    int lane = tid & 31, wid = tid >> 5;
#pragma unroll
    for (int o = 16; o; o >>= 1) {
        s += __shfl_xor_sync(0xffffffffu, s, o);
        sq += __shfl_xor_sync(0xffffffffu, sq, o);
    }
    if (lane == 0) { sh[wid] = s; sh[8 + wid] = sq; }
    __syncthreads();
    if (tid < 32) {
        float rs = (lane < 8) ? sh[lane] : 0.f;
        float rq = (lane < 8) ? sh[8 + lane] : 0.f;
#pragma unroll
        for (int o = 4; o; o >>= 1) {
            rs += __shfl_xor_sync(0xffffffffu, rs, o);
            rq += __shfl_xor_sync(0xffffffffu, rq, o);
        }
        if (lane == 0) { sh[0] = rs; sh[1] = rq; }
    }
    __syncthreads();
    float mu = sh[0] * (1.f / Dd);
    float var = sh[1] * (1.f / Dd) - mu * mu;
    float inv = rsqrtf(var + 1e-6f);
    __syncthreads();

    float4 g4 = reinterpret_cast<const float4*>(gamma)[tid];
    float4 b4 = reinterpret_cast<const float4*>(beta)[tid];
    float h0 = (v0 - mu) * inv * g4.x + b4.x;
    float h1 = (v1 - mu) * inv * g4.y + b4.y;
    float h2 = (v2 - mu) * inv * g4.z + b4.z;
    float h3 = (v3 - mu) * inv * g4.w + b4.w;
    float4 o4; o4.x = h0; o4.y = h1; o4.z = h2; o4.w = h3;
    reinterpret_cast<float4*>(h + (size_t)row * Dd)[tid] = o4;

    __half th0, tl0, th1, tl1, th2, tl2, th3, tl3;
    split2h(h0, th0, tl0); split2h(h1, th1, tl1);
    split2h(h2, th2, tl2); split2h(h3, th3, tl3);
    __half2 p0, p1, q0, q1;
    p0.x = th0; p0.y = th1; p1.x = th2; p1.y = th3;
    q0.x = tl0; q0.y = tl1; q1.x = tl2; q1.y = tl3;
    reinterpret_cast<__half2*>(hh + (size_t)row * Dd)[tid * 2] = p0;
    reinterpret_cast<__half2*>(hh + (size_t)row * Dd)[tid * 2 + 1] = p1;
    reinterpret_cast<__half2*>(hl + (size_t)row * Dd)[tid * 2] = q0;
    reinterpret_cast<__half2*>(hl + (size_t)row * Dd)[tid * 2 + 1] = q1;

    float4 w4 = reinterpret_cast<const float4*>(Wg)[tid];
    float gd = h0 * w4.x + h1 * w4.y + h2 * w4.z + h3 * w4.w;
#pragma unroll
    for (int o = 16; o; o >>= 1) gd += __shfl_xor_sync(0xffffffffu, gd, o);
    if (lane == 0) sh[wid] = gd;
    __syncthreads();
    if (tid == 0) {
        float t = 0.f;
#pragma unroll
        for (int wv = 0; wv < 8; wv++) t += sh[wv];
        gate[row] = 1.f / (1.f + __expf(-(t + bg[0])));
    }
}

__global__ void __launch_bounds__(512)
aggregate_kernel(const float* __restrict__ w, const float* __restrict__ vec,
                 float* __restrict__ part) {
    int blk = blockIdx.x;
    int tid = threadIdx.x;
    int j = tid >> 3;
    int sb = tid & 7;
    float acc[64];
#pragma unroll
    for (int t = 0; t < 64; t++) acc[t] = 0.f;
    __shared__ float ws[64];
    __shared__ float vs[Ss];
    int r0 = blk * AGG_ROWS;
    for (int r = 0; r < AGG_ROWS; r++) {
        size_t row = r0 + r;
        __syncthreads();
        if (tid < 64) ws[tid] = w[row * 64 + tid];
        if (tid < 512) vs[tid] = vec[row * Ss + tid];
        __syncthreads();
        float wv = ws[j];
#pragma unroll
        for (int t = 0; t < 64; t++) acc[t] += wv * vs[sb + 8 * t];
    }
    float* p = part + (size_t)blk * (Kslots * Ss) + j * Ss;
#pragma unroll
    for (int t = 0; t < 64; t++) p[sb + 8 * t] = acc[t];
}

__global__ void finalize_kernel(const float* __restrict__ state, float* __restrict__ out) {
    int e = blockIdx.x * blockDim.x + threadIdx.x;
    if (e >= Kslots * Ss) return;
    float se = 0.f, sw = 0.f;
    for (int r = 0; r < AGG_BLOCKS; r++) {
        se += g_partE[(size_t)r * (Kslots * Ss) + e];
        sw += g_partW[(size_t)r * (Kslots * Ss) + e];
    }
    float ea = fminf(fmaxf(se, 0.f), 1.f);
    out[e] = state[e] * (1.f - ea) + sw;
}

// ======================= launcher ============================================
extern "C" void kernel_launch(void* const* d_in, const int* in_sizes, int n_in,
                              void* d_out, int out_size) {
    const float* nf    = (const float*)d_in[0];
    const float* state = (const float*)d_in[1];
    const float* Wq    = (const float*)d_in[2];
    const float* Wk    = (const float*)d_in[3];
    const float* Wv    = (const float*)d_in[4];
    const float* Wo    = (const float*)d_in[5];
    const float* gam   = (const float*)d_in[6];
    const float* bet   = (const float*)d_in[7];
    const float* Wa    = (const float*)d_in[8];
    const float* Wg    = (const float*)d_in[9];
    const float* bg    = (const float*)d_in[10];
    const float* We    = (const float*)d_in[11];
    const float* be    = (const float*)d_in[12];
    const float* Wc    = (const float*)d_in[13];
    const float* bc    = (const float*)d_in[14];

    float* h_out  = (float*)d_out;
    float* ns_out = (float*)d_out + (size_t)Nn * Dd;

    auto sym = [](const void* s) {
        void* p = nullptr;
        cudaGetSymbolAddress(&p, s);
        return p;
    };
    __half* xh  = (__half*)sym(g_xh);
    __half* xl  = (__half*)sym(g_xl);
    __half* qh  = (__half*)sym(g_qh);
    __half* ql  = (__half*)sym(g_ql);
    __half* ath = (__half*)sym(g_ath);
    __half* atl = (__half*)sym(g_atl);
    __half* rh  = (__half*)sym(g_rh);
    __half* rl  = (__half*)sym(g_rl);
    __half* hh  = (__half*)sym(g_hh);
    __half* hl  = (__half*)sym(g_hl);
    float* ro    = (float*)sym(g_ro);
    float* logit = (float*)sym(g_logits);
    float* ers   = (float*)sym(g_erase);
    float* cnt   = (float*)sym(g_content);
    float* wtd   = (float*)sym(g_weighted);
    float* gate  = (float*)sym(g_gate);
    float* pE    = (float*)sym(g_partE);
    float* pW    = (float*)sym(g_partW);
    __half* wqT  = (__half*)sym(g_wqT);
    __half* woT  = (__half*)sym(g_woT);
    __half* wall = (__half*)sym(g_wall);
    __half* kp   = (__half*)sym(g_kp);
    __half* vT   = (__half*)sym(g_vT);
    __half* st   = (__half*)sym(g_st);
    const size_t SD = (size_t)Ss * Dd;

    // smem: 2 stages * NROWS*144 + 1024 alignment pad
    const int SM_BIG   = 2 * ((2 * 128 + 128) * 144) + 1024;  // 111616
    const int SM_SMALL = 2 * ((2 * 128 + 64) * 144) + 1024;   //  93184
    cudaFuncSetAttribute(hgemm<128, 0>, cudaFuncAttributeMaxDynamicSharedMemorySize, SM_BIG);
    cudaFuncSetAttribute(hgemm<128, 4>, cudaFuncAttributeMaxDynamicSharedMemorySize, SM_BIG);
    cudaFuncSetAttribute(hgemm<128, 5>, cudaFuncAttributeMaxDynamicSharedMemorySize, SM_BIG);
    cudaFuncSetAttribute(hgemm<64, 0>, cudaFuncAttributeMaxDynamicSharedMemorySize, SM_SMALL);
    cudaFuncSetAttribute(hgemm<64, 1>, cudaFuncAttributeMaxDynamicSharedMemorySize, SM_SMALL);

    const float scale = 0.044194173824159216f;  // 1/sqrt(512)

    // ---- prep ----
    convert_split_kernel<<<(Nn * (Dd / 4)) / 256, 256>>>(nf, xh, xl, (size_t)Nn * Dd / 4);
    transpose_h_kernel<<<dim3(Ss / 32, Dd / 32), dim3(32, 8)>>>(Wq, wqT, Dd, Ss);
    transpose_h_kernel<<<dim3(Dd / 32, Ss / 32), dim3(32, 8)>>>(Wo, woT, Ss, Dd);
    transpose_h_kernel<<<dim3(Ss / 32, Dd / 32), dim3(32, 8)>>>(Wa, wall, Dd, Ss);
    transpose_h_kernel<<<dim3(Ss / 32, Dd / 32), dim3(32, 8)>>>(We, wall + SD, Dd, Ss);
    transpose_h_kernel<<<dim3(Ss / 32, Dd / 32), dim3(32, 8)>>>(Wc, wall + 2 * SD, Dd, Ss);
    kv_kernel<<<Kslots, 256>>>(state, Wk, Wv);

    // ---- read path ----
    hgemm<128, 4><<<dim3(4, 512), 256, SM_BIG>>>(
        xh, xl, wqT, Dd, Ss, nullptr, nullptr, qh, ql, nullptr, nullptr, 0.f);
    hgemm<64, 1><<<dim3(1, 512), 256, SM_SMALL>>>(
        qh, ql, kp, Ss, 64, logit, nullptr, nullptr, nullptr, nullptr, nullptr, scale);
    softmax_kernel<true><<<Nn / 8, dim3(32, 8)>>>(logit, nullptr, ath, atl, nullptr);
    hgemm<128, 4><<<dim3(4, 512), 256, SM_BIG>>>(
        ath, atl, vT, Kslots, Ss, nullptr, nullptr, rh, rl, nullptr, nullptr, 0.f);
    hgemm<128, 0><<<dim3(8, 512), 256, SM_BIG>>>(
        rh, rl, woT, Ss, Dd, ro, nullptr, nullptr, nullptr, nullptr, nullptr, 0.f);
    ln_gate_kernel<<<Nn, 256>>>(nf, ro, gam, bet, Wg, bg, h_out, hh, hl, gate);

    // ---- write path: fused h@[Wa|We|Wc] ----
    hgemm<128, 5><<<dim3(12, 512), 256, SM_BIG>>>(
        hh, hl, wall, Dd, 3 * Ss, ers, cnt, qh, ql, be, bc, 0.f);
    hgemm<64, 0><<<dim3(1, 512), 256, SM_SMALL>>>(
        qh, ql, st, Ss, 64, logit, nullptr, nullptr, nullptr, nullptr, nullptr, 0.f);
    softmax_kernel<false><<<Nn / 8, dim3(32, 8)>>>(logit, gate, nullptr, nullptr, wtd);
    aggregate_kernel<<<AGG_BLOCKS, 512>>>(wtd, ers, pE);
    aggregate_kernel<<<AGG_BLOCKS, 512>>>(wtd, cnt, pW);
    finalize_kernel<<<(Kslots * Ss + 255) / 256, 256>>>(state, ns_out);
}

// round 6
// speedup vs baseline: 1.4150x; 1.4150x over previous
#include <cuda_runtime.h>
#include <cuda_fp16.h>
#include <math.h>
#include <stdint.h>

#define Nn 65536
#define Dd 1024
#define Ss 512
#define Kslots 64
#define AGG_BLOCKS 256
#define AGG_ROWS (Nn / AGG_BLOCKS)

// ======================= helpers =============================================
__device__ __forceinline__ uint32_t smem_u32(const void* p) {
    uint32_t a;
    asm("{ .reg .u64 t; cvta.to.shared.u64 t, %1; cvt.u32.u64 %0, t; }" : "=r"(a) : "l"(p));
    return a;
}
__device__ __forceinline__ void cp16(uint32_t dst, const void* src) {
    asm volatile("cp.async.cg.shared.global [%0], [%1], 16;" :: "r"(dst), "l"(src));
}
__device__ __forceinline__ void ldsm4(uint32_t* r, uint32_t addr) {
    asm volatile("ldmatrix.sync.aligned.m8n8.x4.shared.b16 {%0,%1,%2,%3}, [%4];"
                 : "=r"(r[0]), "=r"(r[1]), "=r"(r[2]), "=r"(r[3]) : "r"(addr));
}
__device__ __forceinline__ void hmma16(float* c, const uint32_t* a, const uint32_t* b) {
    asm volatile(
        "mma.sync.aligned.m16n8k16.row.col.f32.f16.f16.f32 "
        "{%0,%1,%2,%3}, {%4,%5,%6,%7}, {%8,%9}, {%0,%1,%2,%3};"
        : "+f"(c[0]), "+f"(c[1]), "+f"(c[2]), "+f"(c[3])
        : "r"(a[0]), "r"(a[1]), "r"(a[2]), "r"(a[3]), "r"(b[0]), "r"(b[1]));
}
__device__ __forceinline__ void split2h(float x, __half& h, __half& l) {
    h = __float2half(x);
    l = __float2half(x - __half2float(h));
}

// ======================= device global scratch ===============================
__device__ __align__(1024) __half g_xh[(size_t)Nn * Dd], g_xl[(size_t)Nn * Dd];
__device__ __align__(1024) __half g_qh[(size_t)Nn * Ss], g_ql[(size_t)Nn * Ss];
__device__ __align__(1024) __half g_ath[(size_t)Nn * Kslots], g_atl[(size_t)Nn * Kslots];
__device__ __align__(1024) __half g_rh[(size_t)Nn * Ss], g_rl[(size_t)Nn * Ss];
__device__ __align__(1024) __half g_hh[(size_t)Nn * Dd], g_hl[(size_t)Nn * Dd];
__device__ __align__(1024) float g_ro[(size_t)Nn * Dd];
__device__ __align__(1024) float g_logits[(size_t)Nn * Kslots];
__device__ __align__(1024) float g_erase[(size_t)Nn * Ss];
__device__ __align__(1024) float g_content[(size_t)Nn * Ss];
__device__ __align__(1024) float g_weighted[(size_t)Nn * Kslots];
__device__ float g_gate[Nn];
__device__ __align__(1024) float g_partE[(size_t)AGG_BLOCKS * Kslots * Ss];
__device__ __align__(1024) float g_partW[(size_t)AGG_BLOCKS * Kslots * Ss];
// B-side (weights), single-plane fp16, [n,k] K-major
__device__ __align__(1024) __half g_wqT[(size_t)Ss * Dd];
__device__ __align__(1024) __half g_woT[(size_t)Dd * Ss];
__device__ __align__(1024) __half g_wall[(size_t)(3 * Ss) * Dd];   // [Wa;We;Wc]^T
__device__ __align__(1024) __half g_kp[(size_t)Kslots * Ss];       // Kp  [64,512]
__device__ __align__(1024) __half g_vT[(size_t)Ss * Kslots];       // V^T [512,64]
__device__ __align__(1024) __half g_st[(size_t)Kslots * Ss];       // state [64,512]

// ======================= fp16 2-term split GEMM (mma.sync) ===================
// C[M,Nc] = act( (Ah+Al) @ B^T );  A,B stored [rows,K] K-major fp16.
// 2-term: Ah*B + Al*B, fp32 accumulate. R3-proven loader: cp.async 16B + swizzle.
// MODE: 0 fp32, 1 fp32*scale, 4 split fp16 out,
//       5 fused-triple over Nc=1536: seg0 split fp16, seg1 sigmoid+bias, seg2 tanh+bias2
template <int BM, int BN, int MODE>
__global__ void __launch_bounds__(256, 2)
hgemm(const __half* __restrict__ Ah, const __half* __restrict__ Al,
      const __half* __restrict__ B,
      int Kd, int Nc,
      float* __restrict__ Cf, float* __restrict__ Cf2,
      __half* __restrict__ Chi, __half* __restrict__ Clo,
      const float* __restrict__ bias, const float* __restrict__ bias2, float scale)
{
    constexpr int NWN = (BN >= 128) ? 4 : 2;
    constexpr int NWM = 8 / NWN;
    constexpr int WM = BM / NWM;        // 64 or 32
    constexpr int MF = WM / 16;         // 4 or 2
    constexpr int NF = (BN / NWN) / 8;  // 4
    constexpr int APL = BM * 128;       // bytes per A plane per stage (K-chunk 64)
    constexpr int BPL = BN * 128;
    constexpr int STAGE = 2 * APL + BPL;
    constexpr int SEGS = (2 * BM + BN) * 8;
    constexpr int SPT = SEGS / 256;

    extern __shared__ char smem_raw[];
    uint32_t sb0 = smem_u32(smem_raw);

    int tid = threadIdx.x, w = tid >> 5, lane = tid & 31;
    int row0 = blockIdx.y * BM, col0 = blockIdx.x * BN;
    int wm0 = (w / NWN) * WM, wn0 = (w % NWN) * (BN / NWN);
    int nch = Kd >> 6;

    float acc[MF][NF][4];
#pragma unroll
    for (int i = 0; i < MF; i++)
#pragma unroll
        for (int j = 0; j < NF; j++)
#pragma unroll
            for (int u = 0; u < 4; u++) acc[i][j][u] = 0.f;

    auto issue = [&](int c) {
        uint32_t sbase = sb0 + (c & 1) * STAGE;
        int k0 = c << 6;
#pragma unroll
        for (int i = 0; i < SPT; i++) {
            int sg = i * 256 + tid;
            int rr = sg >> 3, q = sg & 7;
            const __half* srcp;
            uint32_t dstb;
            int lr;
            if (rr < 2 * BM) {
                int pl = rr >= BM;
                lr = rr - pl * BM;
                srcp = (pl ? Al : Ah) + (size_t)(row0 + lr) * Kd + k0 + q * 8;
                dstb = sbase + pl * APL;
            } else {
                lr = rr - 2 * BM;
                srcp = B + (size_t)(col0 + lr) * Kd + k0 + q * 8;
                dstb = sbase + 2 * APL;
            }
            uint32_t off = (uint32_t)(lr * 128 + q * 16);
            off ^= (off >> 3) & 0x70;
            cp16(dstb + off, (const void*)srcp);
        }
        asm volatile("cp.async.commit_group;");
    };

    issue(0);
    for (int c = 0; c < nch; c++) {
        if (c + 1 < nch) {
            issue(c + 1);
            asm volatile("cp.async.wait_group 1;");
        } else {
            asm volatile("cp.async.wait_group 0;");
        }
        __syncthreads();

        uint32_t sA = sb0 + (c & 1) * STAGE;
        uint32_t sAl = sA + APL, sB = sA + 2 * APL;
#pragma unroll
        for (int ks = 0; ks < 4; ks++) {
            uint32_t ah[MF][4], al_[MF][4];
#pragma unroll
            for (int i = 0; i < MF; i++) {
                uint32_t off = (uint32_t)((wm0 + i * 16 + (lane & 15)) * 128 +
                                          ks * 32 + ((lane >> 4) << 4));
                off ^= (off >> 3) & 0x70;
                ldsm4(ah[i], sA + off);
                ldsm4(al_[i], sAl + off);
            }
            uint32_t b[NF][2];
#pragma unroll
            for (int j2 = 0; j2 < NF / 2; j2++) {
                uint32_t off = (uint32_t)((wn0 + j2 * 16 + (lane & 7) + ((lane >> 4) << 3)) * 128 +
                                          ks * 32 + (((lane >> 3) & 1) << 4));
                off ^= (off >> 3) & 0x70;
                uint32_t t[4];
                ldsm4(t, sB + off);
                b[2 * j2][0] = t[0]; b[2 * j2][1] = t[1];
                b[2 * j2 + 1][0] = t[2]; b[2 * j2 + 1][1] = t[3];
            }
#pragma unroll
            for (int i = 0; i < MF; i++)
#pragma unroll
                for (int j = 0; j < NF; j++) hmma16(acc[i][j], ah[i], b[j]);
#pragma unroll
            for (int i = 0; i < MF; i++)
#pragma unroll
                for (int j = 0; j < NF; j++) hmma16(acc[i][j], al_[i], b[j]);
        }
        __syncthreads();
    }

    // ---- epilogue ----
    int seg = col0 >> 9;   // MODE 5: uniform per CTA (BN=128 divides 512)
#pragma unroll
    for (int i = 0; i < MF; i++) {
#pragma unroll
        for (int j = 0; j < NF; j++) {
            int r = row0 + wm0 + i * 16 + (lane >> 2);
            int cp = col0 + wn0 + j * 8 + ((lane & 3) << 1);
#pragma unroll
            for (int half = 0; half < 2; half++) {
                int rr = r + half * 8;
                float x0 = acc[i][j][half * 2 + 0];
                float x1 = acc[i][j][half * 2 + 1];
                if (MODE == 4) {
                    __half h0, l0, h1, l1;
                    split2h(x0, h0, l0);
                    split2h(x1, h1, l1);
                    __half2 ph; ph.x = h0; ph.y = h1;
                    __half2 pl; pl.x = l0; pl.y = l1;
                    *reinterpret_cast<__half2*>(&Chi[(size_t)rr * Nc + cp]) = ph;
                    *reinterpret_cast<__half2*>(&Clo[(size_t)rr * Nc + cp]) = pl;
                } else if (MODE == 5) {
                    int colL = cp - seg * 512;
                    if (seg == 0) {
                        __half h0, l0, h1, l1;
                        split2h(x0, h0, l0);
                        split2h(x1, h1, l1);
                        __half2 ph; ph.x = h0; ph.y = h1;
                        __half2 pl; pl.x = l0; pl.y = l1;
                        *reinterpret_cast<__half2*>(&Chi[(size_t)rr * Ss + colL]) = ph;
                        *reinterpret_cast<__half2*>(&Clo[(size_t)rr * Ss + colL]) = pl;
                    } else if (seg == 1) {
                        float2 o;
                        o.x = 1.f / (1.f + __expf(-(x0 + bias[colL])));
                        o.y = 1.f / (1.f + __expf(-(x1 + bias[colL + 1])));
                        *reinterpret_cast<float2*>(&Cf[(size_t)rr * Ss + colL]) = o;
                    } else {
                        float2 o;
                        o.x = tanhf(x0 + bias2[colL]);
                        o.y = tanhf(x1 + bias2[colL + 1]);
                        *reinterpret_cast<float2*>(&Cf2[(size_t)rr * Ss + colL]) = o;
                    }
                } else {
                    if (MODE == 1) { x0 *= scale; x1 *= scale; }
                    float2 o; o.x = x0; o.y = x1;
                    *reinterpret_cast<float2*>(&Cf[(size_t)rr * Nc + cp]) = o;
                }
            }
        }
    }
}

// ======================= prep / elementwise kernels ==========================
__global__ void convert_split_kernel(const float* __restrict__ in,
                                     __half* __restrict__ oh, __half* __restrict__ ol,
                                     size_t n4) {
    size_t i = (size_t)blockIdx.x * blockDim.x + threadIdx.x;
    if (i >= n4) return;
    float4 v = reinterpret_cast<const float4*>(in)[i];
    __half h0, l0, h1, l1, h2, l2, h3, l3;
    split2h(v.x, h0, l0); split2h(v.y, h1, l1);
    split2h(v.z, h2, l2); split2h(v.w, h3, l3);
    __half2 a, b, c, d;
    a.x = h0; a.y = h1; b.x = h2; b.y = h3;
    c.x = l0; c.y = l1; d.x = l2; d.y = l3;
    reinterpret_cast<__half2*>(oh)[i * 2] = a;
    reinterpret_cast<__half2*>(oh)[i * 2 + 1] = b;
    reinterpret_cast<__half2*>(ol)[i * 2] = c;
    reinterpret_cast<__half2*>(ol)[i * 2 + 1] = d;
}

__global__ void transpose_h_kernel(const float* __restrict__ W,
                                   __half* __restrict__ T, int R, int C) {
    __shared__ float t[32][33];
    int c0 = blockIdx.x * 32, r0 = blockIdx.y * 32;
    int tx = threadIdx.x, ty = threadIdx.y;
#pragma unroll
    for (int i = 0; i < 32; i += 8)
        t[ty + i][tx] = W[(size_t)(r0 + ty + i) * C + c0 + tx];
    __syncthreads();
#pragma unroll
    for (int i = 0; i < 32; i += 8)
        T[(size_t)(c0 + ty + i) * R + r0 + tx] = __float2half(t[tx][ty + i]);
}

__global__ void kv_kernel(const float* __restrict__ state,
                          const float* __restrict__ Wk,
                          const float* __restrict__ Wv) {
    int j = blockIdx.x;
    __shared__ float srow[Ss];
    for (int c = threadIdx.x; c < Ss; c += blockDim.x) srow[c] = state[j * Ss + c];
    __syncthreads();
    for (int c = threadIdx.x; c < Ss; c += blockDim.x) {
        float ak = 0.f, av = 0.f;
        for (int t = 0; t < Ss; t++) {
            float s = srow[t];
            ak += s * Wk[t * Ss + c];
            av += s * Wv[t * Ss + c];
        }
        g_kp[j * Ss + c] = __float2half(ak);
        g_vT[c * Kslots + j] = __float2half(av);
        g_st[j * Ss + c] = __float2half(srow[c]);
    }
}

template <bool SPLIT_OUT>
__global__ void softmax_kernel(const float* __restrict__ logits,
                               const float* __restrict__ gate,
                               __half* __restrict__ oh, __half* __restrict__ ol,
                               float* __restrict__ of) {
    int row = blockIdx.x * blockDim.y + threadIdx.y;
    int lane = threadIdx.x;
    float v0 = logits[(size_t)row * 64 + lane];
    float v1 = logits[(size_t)row * 64 + 32 + lane];
    float m = fmaxf(v0, v1);
#pragma unroll
    for (int o = 16; o; o >>= 1) m = fmaxf(m, __shfl_xor_sync(0xffffffffu, m, o));
    float e0 = __expf(v0 - m), e1 = __expf(v1 - m);
    float s = e0 + e1;
#pragma unroll
    for (int o = 16; o; o >>= 1) s += __shfl_xor_sync(0xffffffffu, s, o);
    float inv = 1.f / s;
    if (!SPLIT_OUT) inv *= gate[row];
    float a0 = e0 * inv, a1 = e1 * inv;
    if (SPLIT_OUT) {
        __half h, l;
        split2h(a0, h, l);
        oh[(size_t)row * 64 + lane] = h; ol[(size_t)row * 64 + lane] = l;
        split2h(a1, h, l);
        oh[(size_t)row * 64 + 32 + lane] = h; ol[(size_t)row * 64 + 32 + lane] = l;
    } else {
        of[(size_t)row * 64 + lane] = a0;
        of[(size_t)row * 64 + 32 + lane] = a1;
    }
}

__global__ void ln_gate_kernel(const float* __restrict__ nf,
                               const float* __restrict__ ro,
                               const float* __restrict__ gamma,
                               const float* __restrict__ beta,
                               const float* __restrict__ Wg,
                               const float* __restrict__ bg,
                               float* __restrict__ h,
                               __half* __restrict__ hh, __half* __restrict__ hl,
                               float* __restrict__ gate) {
    int row = blockIdx.x;
    int tid = threadIdx.x;
    __shared__ float sh[16];
    float4 a = reinterpret_cast<const float4*>(nf + (size_t)row * Dd)[tid];
    float4 b = reinterpret_cast<const float4*>(ro + (size_t)row * Dd)[tid];
    float v0 = a.x + b.x, v1 = a.y + b.y, v2 = a.z + b.z, v3 = a.w + b.w;
    float s = v0 + v1 + v2 + v3;
    float sq = v0 * v0 + v1 * v1 + v2 * v2 + v3 * v3;
    int lane = tid & 31, wid = tid >> 5;
#pragma unroll
    for (int o = 16; o; o >>= 1) {
        s += __shfl_xor_sync(0xffffffffu, s, o);
        sq += __shfl_xor_sync(0xffffffffu, sq, o);
    }
    if (lane == 0) { sh[wid] = s; sh[8 + wid] = sq; }
    __syncthreads();
    if (tid < 32) {
        float rs = (lane < 8) ? sh[lane] : 0.f;
        float rq = (lane < 8) ? sh[8 + lane] : 0.f;
#pragma unroll
        for (int o = 4; o; o >>= 1) {
            rs += __shfl_xor_sync(0xffffffffu, rs, o);
            rq += __shfl_xor_sync(0xffffffffu, rq, o);
        }
        if (lane == 0) { sh[0] = rs; sh[1] = rq; }
    }
    __syncthreads();
    float mu = sh[0] * (1.f / Dd);
    float var = sh[1] * (1.f / Dd) - mu * mu;
    float inv = rsqrtf(var + 1e-6f);
    __syncthreads();

    float4 g4 = reinterpret_cast<const float4*>(gamma)[tid];
    float4 b4 = reinterpret_cast<const float4*>(beta)[tid];
    float h0 = (v0 - mu) * inv * g4.x + b4.x;
    float h1 = (v1 - mu) * inv * g4.y + b4.y;
    float h2 = (v2 - mu) * inv * g4.z + b4.z;
    float h3 = (v3 - mu) * inv * g4.w + b4.w;
    float4 o4; o4.x = h0; o4.y = h1; o4.z = h2; o4.w = h3;
    reinterpret_cast<float4*>(h + (size_t)row * Dd)[tid] = o4;

    __half th0, tl0, th1, tl1, th2, tl2, th3, tl3;
    split2h(h0, th0, tl0); split2h(h1, th1, tl1);
    split2h(h2, th2, tl2); split2h(h3, th3, tl3);
    __half2 p0, p1, q0, q1;
    p0.x = th0; p0.y = th1; p1.x = th2; p1.y = th3;
    q0.x = tl0; q0.y = tl1; q1.x = tl2; q1.y = tl3;
    reinterpret_cast<__half2*>(hh + (size_t)row * Dd)[tid * 2] = p0;
    reinterpret_cast<__half2*>(hh + (size_t)row * Dd)[tid * 2 + 1] = p1;
    reinterpret_cast<__half2*>(hl + (size_t)row * Dd)[tid * 2] = q0;
    reinterpret_cast<__half2*>(hl + (size_t)row * Dd)[tid * 2 + 1] = q1;

    float4 w4 = reinterpret_cast<const float4*>(Wg)[tid];
    float gd = h0 * w4.x + h1 * w4.y + h2 * w4.z + h3 * w4.w;
#pragma unroll
    for (int o = 16; o; o >>= 1) gd += __shfl_xor_sync(0xffffffffu, gd, o);
    if (lane == 0) sh[wid] = gd;
    __syncthreads();
    if (tid == 0) {
        float t = 0.f;
#pragma unroll
        for (int wv = 0; wv < 8; wv++) t += sh[wv];
        gate[row] = 1.f / (1.f + __expf(-(t + bg[0])));
    }
}

__global__ void __launch_bounds__(512)
aggregate_kernel(const float* __restrict__ w, const float* __restrict__ vec,
                 float* __restrict__ part) {
    int blk = blockIdx.x;
    int tid = threadIdx.x;
    int j = tid >> 3;
    int sb = tid & 7;
    float acc[64];
#pragma unroll
    for (int t = 0; t < 64; t++) acc[t] = 0.f;
    __shared__ float ws[64];
    __shared__ float vs[Ss];
    int r0 = blk * AGG_ROWS;
    for (int r = 0; r < AGG_ROWS; r++) {
        size_t row = r0 + r;
        __syncthreads();
        if (tid < 64) ws[tid] = w[row * 64 + tid];
        if (tid < 512) vs[tid] = vec[row * Ss + tid];
        __syncthreads();
        float wv = ws[j];
#pragma unroll
        for (int t = 0; t < 64; t++) acc[t] += wv * vs[sb + 8 * t];
    }
    float* p = part + (size_t)blk * (Kslots * Ss) + j * Ss;
#pragma unroll
    for (int t = 0; t < 64; t++) p[sb + 8 * t] = acc[t];
}

__global__ void finalize_kernel(const float* __restrict__ state, float* __restrict__ out) {
    int e = blockIdx.x * blockDim.x + threadIdx.x;
    if (e >= Kslots * Ss) return;
    float se = 0.f, sw = 0.f;
    for (int r = 0; r < AGG_BLOCKS; r++) {
        se += g_partE[(size_t)r * (Kslots * Ss) + e];
        sw += g_partW[(size_t)r * (Kslots * Ss) + e];
    }
    float ea = fminf(fmaxf(se, 0.f), 1.f);
    out[e] = state[e] * (1.f - ea) + sw;
}

// ======================= launcher ============================================
extern "C" void kernel_launch(void* const* d_in, const int* in_sizes, int n_in,
                              void* d_out, int out_size) {
    const float* nf    = (const float*)d_in[0];
    const float* state = (const float*)d_in[1];
    const float* Wq    = (const float*)d_in[2];
    const float* Wk    = (const float*)d_in[3];
    const float* Wv    = (const float*)d_in[4];
    const float* Wo    = (const float*)d_in[5];
    const float* gam   = (const float*)d_in[6];
    const float* bet   = (const float*)d_in[7];
    const float* Wa    = (const float*)d_in[8];
    const float* Wg    = (const float*)d_in[9];
    const float* bg    = (const float*)d_in[10];
    const float* We    = (const float*)d_in[11];
    const float* be    = (const float*)d_in[12];
    const float* Wc    = (const float*)d_in[13];
    const float* bc    = (const float*)d_in[14];

    float* h_out  = (float*)d_out;
    float* ns_out = (float*)d_out + (size_t)Nn * Dd;

    auto sym = [](const void* s) {
        void* p = nullptr;
        cudaGetSymbolAddress(&p, s);
        return p;
    };
    __half* xh  = (__half*)sym(g_xh);
    __half* xl  = (__half*)sym(g_xl);
    __half* qh  = (__half*)sym(g_qh);
    __half* ql  = (__half*)sym(g_ql);
    __half* ath = (__half*)sym(g_ath);
    __half* atl = (__half*)sym(g_atl);
    __half* rh  = (__half*)sym(g_rh);
    __half* rl  = (__half*)sym(g_rl);
    __half* hh  = (__half*)sym(g_hh);
    __half* hl  = (__half*)sym(g_hl);
    float* ro    = (float*)sym(g_ro);
    float* logit = (float*)sym(g_logits);
    float* ers   = (float*)sym(g_erase);
    float* cnt   = (float*)sym(g_content);
    float* wtd   = (float*)sym(g_weighted);
    float* gate  = (float*)sym(g_gate);
    float* pE    = (float*)sym(g_partE);
    float* pW    = (float*)sym(g_partW);
    __half* wqT  = (__half*)sym(g_wqT);
    __half* woT  = (__half*)sym(g_woT);
    __half* wall = (__half*)sym(g_wall);
    __half* kp   = (__half*)sym(g_kp);
    __half* vT   = (__half*)sym(g_vT);
    __half* st   = (__half*)sym(g_st);
    const size_t SD = (size_t)Ss * Dd;

    // smem: 2 stages * (2*A_plane + B_plane); allows 2 CTAs/SM
    const int SM_BIG   = 2 * (2 * 128 * 128 + 128 * 128);  // 98304
    const int SM_SMALL = 2 * (2 * 128 * 128 + 64 * 128);   // 81920
    cudaFuncSetAttribute(hgemm<128, 128, 0>, cudaFuncAttributeMaxDynamicSharedMemorySize, SM_BIG);
    cudaFuncSetAttribute(hgemm<128, 128, 4>, cudaFuncAttributeMaxDynamicSharedMemorySize, SM_BIG);
    cudaFuncSetAttribute(hgemm<128, 128, 5>, cudaFuncAttributeMaxDynamicSharedMemorySize, SM_BIG);
    cudaFuncSetAttribute(hgemm<128, 64, 0>, cudaFuncAttributeMaxDynamicSharedMemorySize, SM_SMALL);
    cudaFuncSetAttribute(hgemm<128, 64, 1>, cudaFuncAttributeMaxDynamicSharedMemorySize, SM_SMALL);

    const float scale = 0.044194173824159216f;  // 1/sqrt(512)

    // ---- prep (ordered so launch #6 = big Q GEMM for ncu -s 5 -c 1) ----
    convert_split_kernel<<<(Nn * (Dd / 4)) / 256, 256>>>(nf, xh, xl, (size_t)Nn * Dd / 4);  // 1
    kv_kernel<<<Kslots, 256>>>(state, Wk, Wv);                                              // 2
    transpose_h_kernel<<<dim3(Ss / 32, Dd / 32), dim3(32, 8)>>>(Wq, wqT, Dd, Ss);           // 3
    transpose_h_kernel<<<dim3(Dd / 32, Ss / 32), dim3(32, 8)>>>(Wo, woT, Ss, Dd);           // 4
    transpose_h_kernel<<<dim3(Ss / 32, Dd / 32), dim3(32, 8)>>>(Wa, wall, Dd, Ss);          // 5

    // ---- read path ----
    hgemm<128, 128, 4><<<dim3(4, 512), 256, SM_BIG>>>(                                       // 6 (profiled)
        xh, xl, wqT, Dd, Ss, nullptr, nullptr, qh, ql, nullptr, nullptr, 0.f);
    transpose_h_kernel<<<dim3(Ss / 32, Dd / 32), dim3(32, 8)>>>(We, wall + SD, Dd, Ss);
    transpose_h_kernel<<<dim3(Ss / 32, Dd / 32), dim3(32, 8)>>>(Wc, wall + 2 * SD, Dd, Ss);
    hgemm<128, 64, 1><<<dim3(1, 512), 256, SM_SMALL>>>(
        qh, ql, kp, Ss, 64, logit, nullptr, nullptr, nullptr, nullptr, nullptr, scale);
    softmax_kernel<true><<<Nn / 8, dim3(32, 8)>>>(logit, nullptr, ath, atl, nullptr);
    hgemm<128, 128, 4><<<dim3(4, 512), 256, SM_BIG>>>(
        ath, atl, vT, Kslots, Ss, nullptr, nullptr, rh, rl, nullptr, nullptr, 0.f);
    hgemm<128, 128, 0><<<dim3(8, 512), 256, SM_BIG>>>(
        rh, rl, woT, Ss, Dd, ro, nullptr, nullptr, nullptr, nullptr, nullptr, 0.f);
    ln_gate_kernel<<<Nn, 256>>>(nf, ro, gam, bet, Wg, bg, h_out, hh, hl, gate);

    // ---- write path: fused h@[Wa|We|Wc] ----
    hgemm<128, 128, 5><<<dim3(12, 512), 256, SM_BIG>>>(
        hh, hl, wall, Dd, 3 * Ss, ers, cnt, qh, ql, be, bc, 0.f);
    hgemm<128, 64, 0><<<dim3(1, 512), 256, SM_SMALL>>>(
        qh, ql, st, Ss, 64, logit, nullptr, nullptr, nullptr, nullptr, nullptr, 0.f);
    softmax_kernel<false><<<Nn / 8, dim3(32, 8)>>>(logit, gate, nullptr, nullptr, wtd);
    aggregate_kernel<<<AGG_BLOCKS, 512>>>(wtd, ers, pE);
    aggregate_kernel<<<AGG_BLOCKS, 512>>>(wtd, cnt, pW);
    finalize_kernel<<<(Kslots * Ss + 255) / 256, 256>>>(state, ns_out);
}

// round 7
// speedup vs baseline: 1.6833x; 1.1896x over previous
#include <cuda_runtime.h>
#include <cuda_fp16.h>
#include <math.h>
#include <stdint.h>

#define Nn 65536
#define Dd 1024
#define Ss 512
#define Kslots 64
#define AGG_BLOCKS 256
#define AGG_ROWS (Nn / AGG_BLOCKS)

// ======================= helpers =============================================
__device__ __forceinline__ uint32_t smem_u32(const void* p) {
    uint32_t a;
    asm("{ .reg .u64 t; cvta.to.shared.u64 t, %1; cvt.u32.u64 %0, t; }" : "=r"(a) : "l"(p));
    return a;
}
__device__ __forceinline__ void cp16(uint32_t dst, const void* src) {
    asm volatile("cp.async.cg.shared.global [%0], [%1], 16;" :: "r"(dst), "l"(src));
}
__device__ __forceinline__ void ldsm4(uint32_t* r, uint32_t addr) {
    asm volatile("ldmatrix.sync.aligned.m8n8.x4.shared.b16 {%0,%1,%2,%3}, [%4];"
                 : "=r"(r[0]), "=r"(r[1]), "=r"(r[2]), "=r"(r[3]) : "r"(addr));
}
__device__ __forceinline__ void hmma16(float* c, const uint32_t* a, const uint32_t* b) {
    asm volatile(
        "mma.sync.aligned.m16n8k16.row.col.f32.f16.f16.f32 "
        "{%0,%1,%2,%3}, {%4,%5,%6,%7}, {%8,%9}, {%0,%1,%2,%3};"
        : "+f"(c[0]), "+f"(c[1]), "+f"(c[2]), "+f"(c[3])
        : "r"(a[0]), "r"(a[1]), "r"(a[2]), "r"(a[3]), "r"(b[0]), "r"(b[1]));
}
__device__ __forceinline__ void split2h(float x, __half& h, __half& l) {
    h = __float2half(x);
    l = __float2half(x - __half2float(h));
}

// ======================= device global scratch ===============================
__device__ __align__(1024) __half g_xh[(size_t)Nn * Dd], g_xl[(size_t)Nn * Dd];
__device__ __align__(1024) __half g_ath[(size_t)Nn * Kslots], g_atl[(size_t)Nn * Kslots];
__device__ __align__(1024) __half g_hh[(size_t)Nn * Dd], g_hl[(size_t)Nn * Dd];
__device__ __align__(1024) float g_ro[(size_t)Nn * Dd];
__device__ __align__(1024) float g_logits[(size_t)Nn * Kslots];
__device__ __align__(1024) float g_erase[(size_t)Nn * Ss];
__device__ __align__(1024) float g_content[(size_t)Nn * Ss];
__device__ __align__(1024) float g_weighted[(size_t)Nn * Kslots];
__device__ float g_gate[Nn];
__device__ __align__(1024) float g_partE[(size_t)AGG_BLOCKS * Kslots * Ss];
__device__ __align__(1024) float g_partW[(size_t)AGG_BLOCKS * Kslots * Ss];
// folded small matrices (fp16, hgemm-B layout [rows][K] K-major)
__device__ __align__(1024) __half g_m1T[(size_t)Kslots * Dd];   // (Wq@Kp^T)^T * scale  [64,1024]
__device__ __align__(1024) __half g_m2T[(size_t)Kslots * Dd];   // (Wa@state^T)^T       [64,1024]
__device__ __align__(1024) __half g_vwoT[(size_t)Dd * Kslots];  // (V@Wo)^T             [1024,64]
__device__ __align__(1024) __half g_wall[(size_t)(2 * Ss) * Dd];// [We^T; Wc^T]         [1024,1024]
// fp32 precompute intermediates
__device__ __align__(1024) float g_Kp32[Kslots * Ss];
__device__ __align__(1024) float g_V32[Kslots * Ss];

// ======================= fp16 2-term split GEMM (mma.sync) ===================
// C[M,Nc] = act( (Ah+Al) @ B^T );  A [M,Kd], B [Nc,Kd] K-major fp16.
// MODE 0: fp32 out to Cf [M,Nc].
// MODE 6: fused-double over Nc=1024: cols [0,512) sigmoid(+bias)->Cf[M,512],
//                                    cols [512,1024) tanh(+bias2)->Cf2[M,512].
template <int BM, int BN, int MODE>
__global__ void __launch_bounds__(256, 2)
hgemm(const __half* __restrict__ Ah, const __half* __restrict__ Al,
      const __half* __restrict__ B,
      int Kd, int Nc,
      float* __restrict__ Cf, float* __restrict__ Cf2,
      const float* __restrict__ bias, const float* __restrict__ bias2)
{
    constexpr int NWN = (BN >= 128) ? 4 : 2;
    constexpr int NWM = 8 / NWN;
    constexpr int WM = BM / NWM;
    constexpr int MF = WM / 16;
    constexpr int NF = (BN / NWN) / 8;
    constexpr int APL = BM * 128;
    constexpr int BPL = BN * 128;
    constexpr int STAGE = 2 * APL + BPL;
    constexpr int SEGS = (2 * BM + BN) * 8;
    constexpr int SPT = SEGS / 256;

    extern __shared__ char smem_raw[];
    uint32_t sb0 = smem_u32(smem_raw);

    int tid = threadIdx.x, w = tid >> 5, lane = tid & 31;
    int row0 = blockIdx.y * BM, col0 = blockIdx.x * BN;
    int wm0 = (w / NWN) * WM, wn0 = (w % NWN) * (BN / NWN);
    int nch = Kd >> 6;

    float acc[MF][NF][4];
#pragma unroll
    for (int i = 0; i < MF; i++)
#pragma unroll
        for (int j = 0; j < NF; j++)
#pragma unroll
            for (int u = 0; u < 4; u++) acc[i][j][u] = 0.f;

    auto issue = [&](int c) {
        uint32_t sbase = sb0 + (c & 1) * STAGE;
        int k0 = c << 6;
#pragma unroll
        for (int i = 0; i < SPT; i++) {
            int sg = i * 256 + tid;
            int rr = sg >> 3, q = sg & 7;
            const __half* srcp;
            uint32_t dstb;
            int lr;
            if (rr < 2 * BM) {
                int pl = rr >= BM;
                lr = rr - pl * BM;
                srcp = (pl ? Al : Ah) + (size_t)(row0 + lr) * Kd + k0 + q * 8;
                dstb = sbase + pl * APL;
            } else {
                lr = rr - 2 * BM;
                srcp = B + (size_t)(col0 + lr) * Kd + k0 + q * 8;
                dstb = sbase + 2 * APL;
            }
            uint32_t off = (uint32_t)(lr * 128 + q * 16);
            off ^= (off >> 3) & 0x70;
            cp16(dstb + off, (const void*)srcp);
        }
        asm volatile("cp.async.commit_group;");
    };

    issue(0);
    for (int c = 0; c < nch; c++) {
        if (c + 1 < nch) {
            issue(c + 1);
            asm volatile("cp.async.wait_group 1;");
        } else {
            asm volatile("cp.async.wait_group 0;");
        }
        __syncthreads();

        uint32_t sA = sb0 + (c & 1) * STAGE;
        uint32_t sAl = sA + APL, sB = sA + 2 * APL;
#pragma unroll
        for (int ks = 0; ks < 4; ks++) {
            uint32_t ah[MF][4], al_[MF][4];
#pragma unroll
            for (int i = 0; i < MF; i++) {
                uint32_t off = (uint32_t)((wm0 + i * 16 + (lane & 15)) * 128 +
                                          ks * 32 + ((lane >> 4) << 4));
                off ^= (off >> 3) & 0x70;
                ldsm4(ah[i], sA + off);
                ldsm4(al_[i], sAl + off);
            }
            uint32_t b[NF][2];
#pragma unroll
            for (int j2 = 0; j2 < NF / 2; j2++) {
                uint32_t off = (uint32_t)((wn0 + j2 * 16 + (lane & 7) + ((lane >> 4) << 3)) * 128 +
                                          ks * 32 + (((lane >> 3) & 1) << 4));
                off ^= (off >> 3) & 0x70;
                uint32_t t[4];
                ldsm4(t, sB + off);
                b[2 * j2][0] = t[0]; b[2 * j2][1] = t[1];
                b[2 * j2 + 1][0] = t[2]; b[2 * j2 + 1][1] = t[3];
            }
#pragma unroll
            for (int i = 0; i < MF; i++)
#pragma unroll
                for (int j = 0; j < NF; j++) hmma16(acc[i][j], ah[i], b[j]);
#pragma unroll
            for (int i = 0; i < MF; i++)
#pragma unroll
                for (int j = 0; j < NF; j++) hmma16(acc[i][j], al_[i], b[j]);
        }
        __syncthreads();
    }

    // ---- epilogue ----
    int seg = col0 >> 9;   // MODE 6: uniform per CTA (BN=128 divides 512)
#pragma unroll
    for (int i = 0; i < MF; i++) {
#pragma unroll
        for (int j = 0; j < NF; j++) {
            int r = row0 + wm0 + i * 16 + (lane >> 2);
            int cp = col0 + wn0 + j * 8 + ((lane & 3) << 1);
#pragma unroll
            for (int half = 0; half < 2; half++) {
                int rr = r + half * 8;
                float x0 = acc[i][j][half * 2 + 0];
                float x1 = acc[i][j][half * 2 + 1];
                if (MODE == 6) {
                    int colL = cp - seg * 512;
                    if (seg == 0) {
                        float2 o;
                        o.x = 1.f / (1.f + __expf(-(x0 + bias[colL])));
                        o.y = 1.f / (1.f + __expf(-(x1 + bias[colL + 1])));
                        *reinterpret_cast<float2*>(&Cf[(size_t)rr * Ss + colL]) = o;
                    } else {
                        float2 o;
                        o.x = tanhf(x0 + bias2[colL]);
                        o.y = tanhf(x1 + bias2[colL + 1]);
                        *reinterpret_cast<float2*>(&Cf2[(size_t)rr * Ss + colL]) = o;
                    }
                } else {
                    float2 o; o.x = x0; o.y = x1;
                    *reinterpret_cast<float2*>(&Cf[(size_t)rr * Nc + cp]) = o;
                }
            }
        }
    }
}

// ======================= prep / elementwise kernels ==========================
__global__ void convert_split_kernel(const float* __restrict__ in,
                                     __half* __restrict__ oh, __half* __restrict__ ol,
                                     size_t n4) {
    size_t i = (size_t)blockIdx.x * blockDim.x + threadIdx.x;
    if (i >= n4) return;
    float4 v = reinterpret_cast<const float4*>(in)[i];
    __half h0, l0, h1, l1, h2, l2, h3, l3;
    split2h(v.x, h0, l0); split2h(v.y, h1, l1);
    split2h(v.z, h2, l2); split2h(v.w, h3, l3);
    __half2 a, b, c, d;
    a.x = h0; a.y = h1; b.x = h2; b.y = h3;
    c.x = l0; c.y = l1; d.x = l2; d.y = l3;
    reinterpret_cast<__half2*>(oh)[i * 2] = a;
    reinterpret_cast<__half2*>(oh)[i * 2 + 1] = b;
    reinterpret_cast<__half2*>(ol)[i * 2] = c;
    reinterpret_cast<__half2*>(ol)[i * 2 + 1] = d;
}

// W[R,C] fp32 -> T[C,R] fp16 (transpose)
__global__ void transpose_h_kernel(const float* __restrict__ W,
                                   __half* __restrict__ T, int R, int C) {
    __shared__ float t[32][33];
    int c0 = blockIdx.x * 32, r0 = blockIdx.y * 32;
    int tx = threadIdx.x, ty = threadIdx.y;
#pragma unroll
    for (int i = 0; i < 32; i += 8)
        t[ty + i][tx] = W[(size_t)(r0 + ty + i) * C + c0 + tx];
    __syncthreads();
#pragma unroll
    for (int i = 0; i < 32; i += 8)
        T[(size_t)(c0 + ty + i) * R + r0 + tx] = __float2half(t[tx][ty + i]);
}

// Kp = state@Wk, V = state@Wv (fp32 [64,512])
__global__ void kv2_kernel(const float* __restrict__ state,
                           const float* __restrict__ Wk,
                           const float* __restrict__ Wv) {
    int j = blockIdx.x;
    __shared__ float srow[Ss];
    for (int c = threadIdx.x; c < Ss; c += blockDim.x) srow[c] = state[j * Ss + c];
    __syncthreads();
    for (int c = threadIdx.x; c < Ss; c += blockDim.x) {
        float ak = 0.f, av = 0.f;
        for (int t = 0; t < Ss; t++) {
            float s = srow[t];
            ak += s * Wk[t * Ss + c];
            av += s * Wv[t * Ss + c];
        }
        g_Kp32[j * Ss + c] = ak;
        g_V32[j * Ss + c] = av;
    }
}

// outT[j, d] = scale * sum_s A[d,s] * Bm[j,s]   (outT: [64 rows][Dd cols] fp16)
__global__ void smallB_kernel(const float* __restrict__ A,
                              const float* __restrict__ Bm,
                              __half* __restrict__ outT, float scale) {
    int d = blockIdx.x, j = threadIdx.x;
    __shared__ float arow[Ss];
    for (int s = j; s < Ss; s += 64) arow[s] = A[(size_t)d * Ss + s];
    __syncthreads();
    float acc = 0.f;
    for (int s = 0; s < Ss; s++) acc += arow[s] * Bm[j * Ss + s];
    outT[(size_t)j * Dd + d] = __float2half(acc * scale);
}

// vwoT[n, v] = sum_s V[v,s] * Wo[s,n]   (vwoT: [1024 rows][64 cols] fp16)
__global__ void vwo_kernel(const float* __restrict__ V,
                           const float* __restrict__ Wo,
                           __half* __restrict__ outT) {
    int n = blockIdx.x, v = threadIdx.x;
    __shared__ float wcol[Ss];
    for (int s = v; s < Ss; s += 64) wcol[s] = Wo[(size_t)s * Dd + n];
    __syncthreads();
    float acc = 0.f;
    for (int s = 0; s < Ss; s++) acc += V[v * Ss + s] * wcol[s];
    outT[(size_t)n * 64 + v] = __float2half(acc);
}

template <bool SPLIT_OUT>
__global__ void softmax_kernel(const float* __restrict__ logits,
                               const float* __restrict__ gate,
                               __half* __restrict__ oh, __half* __restrict__ ol,
                               float* __restrict__ of) {
    int row = blockIdx.x * blockDim.y + threadIdx.y;
    int lane = threadIdx.x;
    float v0 = logits[(size_t)row * 64 + lane];
    float v1 = logits[(size_t)row * 64 + 32 + lane];
    float m = fmaxf(v0, v1);
#pragma unroll
    for (int o = 16; o; o >>= 1) m = fmaxf(m, __shfl_xor_sync(0xffffffffu, m, o));
    float e0 = __expf(v0 - m), e1 = __expf(v1 - m);
    float s = e0 + e1;
#pragma unroll
    for (int o = 16; o; o >>= 1) s += __shfl_xor_sync(0xffffffffu, s, o);
    float inv = 1.f / s;
    if (!SPLIT_OUT) inv *= gate[row];
    float a0 = e0 * inv, a1 = e1 * inv;
    if (SPLIT_OUT) {
        __half h, l;
        split2h(a0, h, l);
        oh[(size_t)row * 64 + lane] = h; ol[(size_t)row * 64 + lane] = l;
        split2h(a1, h, l);
        oh[(size_t)row * 64 + 32 + lane] = h; ol[(size_t)row * 64 + 32 + lane] = l;
    } else {
        of[(size_t)row * 64 + lane] = a0;
        of[(size_t)row * 64 + 32 + lane] = a1;
    }
}

__global__ void ln_gate_kernel(const float* __restrict__ nf,
                               const float* __restrict__ ro,
                               const float* __restrict__ gamma,
                               const float* __restrict__ beta,
                               const float* __restrict__ Wg,
                               const float* __restrict__ bg,
                               float* __restrict__ h,
                               __half* __restrict__ hh, __half* __restrict__ hl,
                               float* __restrict__ gate) {
    int row = blockIdx.x;
    int tid = threadIdx.x;
    __shared__ float sh[16];
    float4 a = reinterpret_cast<const float4*>(nf + (size_t)row * Dd)[tid];
    float4 b = reinterpret_cast<const float4*>(ro + (size_t)row * Dd)[tid];
    float v0 = a.x + b.x, v1 = a.y + b.y, v2 = a.z + b.z, v3 = a.w + b.w;
    float s = v0 + v1 + v2 + v3;
    float sq = v0 * v0 + v1 * v1 + v2 * v2 + v3 * v3;
    int lane = tid & 31, wid = tid >> 5;
#pragma unroll
    for (int o = 16; o; o >>= 1) {
        s += __shfl_xor_sync(0xffffffffu, s, o);
        sq += __shfl_xor_sync(0xffffffffu, sq, o);
    }
    if (lane == 0) { sh[wid] = s; sh[8 + wid] = sq; }
    __syncthreads();
    if (tid < 32) {
        float rs = (lane < 8) ? sh[lane] : 0.f;
        float rq = (lane < 8) ? sh[8 + lane] : 0.f;
#pragma unroll
        for (int o = 4; o; o >>= 1) {
            rs += __shfl_xor_sync(0xffffffffu, rs, o);
            rq += __shfl_xor_sync(0xffffffffu, rq, o);
        }
        if (lane == 0) { sh[0] = rs; sh[1] = rq; }
    }
    __syncthreads();
    float mu = sh[0] * (1.f / Dd);
    float var = sh[1] * (1.f / Dd) - mu * mu;
    float inv = rsqrtf(var + 1e-6f);
    __syncthreads();

    float4 g4 = reinterpret_cast<const float4*>(gamma)[tid];
    float4 b4 = reinterpret_cast<const float4*>(beta)[tid];
    float h0 = (v0 - mu) * inv * g4.x + b4.x;
    float h1 = (v1 - mu) * inv * g4.y + b4.y;
    float h2 = (v2 - mu) * inv * g4.z + b4.z;
    float h3 = (v3 - mu) * inv * g4.w + b4.w;
    float4 o4; o4.x = h0; o4.y = h1; o4.z = h2; o4.w = h3;
    reinterpret_cast<float4*>(h + (size_t)row * Dd)[tid] = o4;

    __half th0, tl0, th1, tl1, th2, tl2, th3, tl3;
    split2h(h0, th0, tl0); split2h(h1, th1, tl1);
    split2h(h2, th2, tl2); split2h(h3, th3, tl3);
    __half2 p0, p1, q0, q1;
    p0.x = th0; p0.y = th1; p1.x = th2; p1.y = th3;
    q0.x = tl0; q0.y = tl1; q1.x = tl2; q1.y = tl3;
    reinterpret_cast<__half2*>(hh + (size_t)row * Dd)[tid * 2] = p0;
    reinterpret_cast<__half2*>(hh + (size_t)row * Dd)[tid * 2 + 1] = p1;
    reinterpret_cast<__half2*>(hl + (size_t)row * Dd)[tid * 2] = q0;
    reinterpret_cast<__half2*>(hl + (size_t)row * Dd)[tid * 2 + 1] = q1;

    float4 w4 = reinterpret_cast<const float4*>(Wg)[tid];
    float gd = h0 * w4.x + h1 * w4.y + h2 * w4.z + h3 * w4.w;
#pragma unroll
    for (int o = 16; o; o >>= 1) gd += __shfl_xor_sync(0xffffffffu, gd, o);
    if (lane == 0) sh[wid] = gd;
    __syncthreads();
    if (tid == 0) {
        float t = 0.f;
#pragma unroll
        for (int wv = 0; wv < 8; wv++) t += sh[wv];
        gate[row] = 1.f / (1.f + __expf(-(t + bg[0])));
    }
}

__global__ void __launch_bounds__(512)
aggregate_kernel(const float* __restrict__ w, const float* __restrict__ vec,
                 float* __restrict__ part) {
    int blk = blockIdx.x;
    int tid = threadIdx.x;
    int j = tid >> 3;
    int sb = tid & 7;
    float acc[64];
#pragma unroll
    for (int t = 0; t < 64; t++) acc[t] = 0.f;
    __shared__ float ws[64];
    __shared__ float vs[Ss];
    int r0 = blk * AGG_ROWS;
    for (int r = 0; r < AGG_ROWS; r++) {
        size_t row = r0 + r;
        __syncthreads();
        if (tid < 64) ws[tid] = w[row * 64 + tid];
        if (tid < 512) vs[tid] = vec[row * Ss + tid];
        __syncthreads();
        float wv = ws[j];
#pragma unroll
        for (int t = 0; t < 64; t++) acc[t] += wv * vs[sb + 8 * t];
    }
    float* p = part + (size_t)blk * (Kslots * Ss) + j * Ss;
#pragma unroll
    for (int t = 0; t < 64; t++) p[sb + 8 * t] = acc[t];
}

__global__ void finalize_kernel(const float* __restrict__ state, float* __restrict__ out) {
    int e = blockIdx.x * blockDim.x + threadIdx.x;
    if (e >= Kslots * Ss) return;
    float se = 0.f, sw = 0.f;
    for (int r = 0; r < AGG_BLOCKS; r++) {
        se += g_partE[(size_t)r * (Kslots * Ss) + e];
        sw += g_partW[(size_t)r * (Kslots * Ss) + e];
    }
    float ea = fminf(fmaxf(se, 0.f), 1.f);
    out[e] = state[e] * (1.f - ea) + sw;
}

// ======================= launcher ============================================
extern "C" void kernel_launch(void* const* d_in, const int* in_sizes, int n_in,
                              void* d_out, int out_size) {
    const float* nf    = (const float*)d_in[0];
    const float* state = (const float*)d_in[1];
    const float* Wq    = (const float*)d_in[2];
    const float* Wk    = (const float*)d_in[3];
    const float* Wv    = (const float*)d_in[4];
    const float* Wo    = (const float*)d_in[5];
    const float* gam   = (const float*)d_in[6];
    const float* bet   = (const float*)d_in[7];
    const float* Wa    = (const float*)d_in[8];
    const float* Wg    = (const float*)d_in[9];
    const float* bg    = (const float*)d_in[10];
    const float* We    = (const float*)d_in[11];
    const float* be    = (const float*)d_in[12];
    const float* Wc    = (const float*)d_in[13];
    const float* bc    = (const float*)d_in[14];

    float* h_out  = (float*)d_out;
    float* ns_out = (float*)d_out + (size_t)Nn * Dd;

    auto sym = [](const void* s) {
        void* p = nullptr;
        cudaGetSymbolAddress(&p, s);
        return p;
    };
    __half* xh   = (__half*)sym(g_xh);
    __half* xl   = (__half*)sym(g_xl);
    __half* ath  = (__half*)sym(g_ath);
    __half* atl  = (__half*)sym(g_atl);
    __half* hh   = (__half*)sym(g_hh);
    __half* hl   = (__half*)sym(g_hl);
    float* ro    = (float*)sym(g_ro);
    float* logit = (float*)sym(g_logits);
    float* ers   = (float*)sym(g_erase);
    float* cnt   = (float*)sym(g_content);
    float* wtd   = (float*)sym(g_weighted);
    float* gate  = (float*)sym(g_gate);
    float* pE    = (float*)sym(g_partE);
    float* pW    = (float*)sym(g_partW);
    __half* m1T  = (__half*)sym(g_m1T);
    __half* m2T  = (__half*)sym(g_m2T);
    __half* vwoT = (__half*)sym(g_vwoT);
    __half* wall = (__half*)sym(g_wall);
    float* Kp32  = (float*)sym(g_Kp32);
    float* V32   = (float*)sym(g_V32);
    const size_t SD = (size_t)Ss * Dd;

    const int SM_BIG   = 2 * (2 * 128 * 128 + 128 * 128);  // 98304
    const int SM_SMALL = 2 * (2 * 128 * 128 + 64 * 128);   // 81920
    cudaFuncSetAttribute(hgemm<128, 128, 0>, cudaFuncAttributeMaxDynamicSharedMemorySize, SM_BIG);
    cudaFuncSetAttribute(hgemm<128, 128, 6>, cudaFuncAttributeMaxDynamicSharedMemorySize, SM_BIG);
    cudaFuncSetAttribute(hgemm<128, 64, 0>, cudaFuncAttributeMaxDynamicSharedMemorySize, SM_SMALL);

    const float scale = 0.044194173824159216f;  // 1/sqrt(512)

    // ---- prep (launch #6 = logits GEMM, profiled by ncu -s 5 -c 1) ----
    convert_split_kernel<<<(Nn * (Dd / 4)) / 256, 256>>>(nf, xh, xl, (size_t)Nn * Dd / 4); // 1
    kv2_kernel<<<Kslots, 256>>>(state, Wk, Wv);                                            // 2
    smallB_kernel<<<Dd, 64>>>(Wq, Kp32, m1T, scale);                                       // 3
    smallB_kernel<<<Dd, 64>>>(Wa, state, m2T, 1.0f);                                       // 4
    vwo_kernel<<<Dd, 64>>>(V32, Wo, vwoT);                                                 // 5

    // ---- read path ----
    hgemm<128, 64, 0><<<dim3(1, 512), 256, SM_SMALL>>>(                                    // 6 (profiled)
        xh, xl, m1T, Dd, 64, logit, nullptr, nullptr, nullptr);
    transpose_h_kernel<<<dim3(Ss / 32, Dd / 32), dim3(32, 8)>>>(We, wall, Dd, Ss);
    transpose_h_kernel<<<dim3(Ss / 32, Dd / 32), dim3(32, 8)>>>(Wc, wall + SD, Dd, Ss);
    softmax_kernel<true><<<Nn / 8, dim3(32, 8)>>>(logit, nullptr, ath, atl, nullptr);
    hgemm<128, 128, 0><<<dim3(8, 512), 256, SM_BIG>>>(
        ath, atl, vwoT, 64, Dd, ro, nullptr, nullptr, nullptr);
    ln_gate_kernel<<<Nn, 256>>>(nf, ro, gam, bet, Wg, bg, h_out, hh, hl, gate);

    // ---- write path ----
    hgemm<128, 64, 0><<<dim3(1, 512), 256, SM_SMALL>>>(
        hh, hl, m2T, Dd, 64, logit, nullptr, nullptr, nullptr);
    softmax_kernel<false><<<Nn / 8, dim3(32, 8)>>>(logit, gate, nullptr, nullptr, wtd);
    hgemm<128, 128, 6><<<dim3(8, 512), 256, SM_BIG>>>(
        hh, hl, wall, Dd, 2 * Ss, ers, cnt, be, bc);
    aggregate_kernel<<<AGG_BLOCKS, 512>>>(wtd, ers, pE);
    aggregate_kernel<<<AGG_BLOCKS, 512>>>(wtd, cnt, pW);
    finalize_kernel<<<(Kslots * Ss + 255) / 256, 256>>>(state, ns_out);
}